// round 14
// baseline (speedup 1.0000x reference)
#include <cuda_runtime.h>
#include <cstdint>

#define THRESH 0.85f
#define NB 4
#define ND 16
#define NN 4096
#define HS 32           // k32 steps per warp (K quarter = 1024)
#define NST 5           // smem ring stages per warp
#define PFD 4           // cp.async prefetch distance (groups in flight)

// A-fragment table (S = tf32(seg), permuted k): [b][c32 0..127][ks 0..3][lane][4]
// physical k = c32*32 + 8*tg + 2*ks + (j>>1); row = gr + 8*(j&1). 1 MB, L2-resident.
__device__ float g_Afrag[NB * 128 * 4 * 32 * 4];

__device__ __forceinline__ uint32_t cvt_tf32(float x) {
    uint32_t u; asm("cvt.rna.tf32.f32 %0, %1;" : "=r"(u) : "f"(x));
    return u;
}
// threshold only; HMMA's tf32 datapath truncates low mantissa bits in HW
__device__ __forceinline__ uint32_t thr(float w) {
    float wt = (w > THRESH) ? w : 0.0f;
    return __float_as_uint(wt);
}
__device__ __forceinline__ void mma_tf32(float (&c)[4], uint32_t a0, uint32_t a1,
                                         uint32_t a2, uint32_t a3,
                                         uint32_t b0, uint32_t b1) {
    asm volatile(
        "mma.sync.aligned.m16n8k8.row.col.f32.tf32.tf32.f32 "
        "{%0,%1,%2,%3}, {%4,%5,%6,%7}, {%8,%9}, {%0,%1,%2,%3};"
        : "+f"(c[0]), "+f"(c[1]), "+f"(c[2]), "+f"(c[3])
        : "r"(a0), "r"(a1), "r"(a2), "r"(a3), "r"(b0), "r"(b1));
}
__device__ __forceinline__ uint32_t fu(float x) { return __float_as_uint(x); }
__device__ __forceinline__ float uf(uint32_t x) { return __uint_as_float(x); }
__device__ __forceinline__ uint32_t smem_u32(const void* p) {
    uint32_t a;
    asm("{ .reg .u64 t; cvta.to.shared.u64 t, %1; cvt.u32.u64 %0, t; }" : "=r"(a) : "l"(p));
    return a;
}
__device__ __forceinline__ void cp16(uint32_t dst, const void* src) {
    asm volatile("cp.async.cg.shared.global [%0], [%1], 16;"
                 :: "r"(dst), "l"(src) : "memory");
}
__device__ __forceinline__ void cp_commit() {
    asm volatile("cp.async.commit_group;" ::: "memory");
}
__device__ __forceinline__ void cp_wait4() {
    asm volatile("cp.async.wait_group 4;" ::: "memory");
}

// ---------------- prologue: build permuted A-fragment table ----------------
__global__ void __launch_bounds__(256) build_afrag_kernel(const float* __restrict__ seg) {
    int idx  = blockIdx.x * 256 + threadIdx.x;    // [b][c][ks][lane], 65536 total
    int lane = idx & 31;
    int ks   = (idx >> 5) & 3;
    int c    = (idx >> 7) & 127;
    int b    = idx >> 14;
    int gr = lane >> 2, tg = lane & 3;
    int k  = c * 32 + 8 * tg + 2 * ks;
    const float* sp = seg + ((size_t)b * ND << 12);
    float4 v;
    v.x = uf(cvt_tf32(sp[((size_t)gr       << 12) + k]));
    v.y = uf(cvt_tf32(sp[((size_t)(gr + 8) << 12) + k]));
    v.z = uf(cvt_tf32(sp[((size_t)gr       << 12) + k + 1]));
    v.w = uf(cvt_tf32(sp[((size_t)(gr + 8) << 12) + k + 1]));
    reinterpret_cast<float4*>(g_Afrag)[idx] = v;
}

// ---------------- main kernel ----------------
// grid = 1024 CTAs (4 b x 256 tiles of 16 m-rows), block = 128 thr = 4 warps.
// Warp w owns K quarter [w*1024,(w+1)*1024) as 32 k32-steps. W is staged via
// cp.async into a per-warp 5-stage smem ring (prefetch distance 4 -> ~128KB/SM
// in flight); fragments read back with XOR-swizzled LDS.128 (conflict-free).
// A fragments double-buffered in registers from the L2-resident table.
__global__ void __launch_bounds__(128, 4) regu_mma_kernel(const float* __restrict__ W,
                                                          float* __restrict__ out) {
    __shared__ __align__(16) float sring[4][NST][16 * 32];   // 4 x 10KB
    __shared__ float sred[3][32][10];
    const int tid  = threadIdx.x;
    const int w    = tid >> 5;
    const int lane = tid & 31;
    const int gr   = lane >> 2;
    const int tg   = lane & 3;
    const int b    = blockIdx.x >> 8;
    const int m0   = (blockIdx.x & 255) << 4;
    const int kq   = w << 10;

    // cp.async source: lane covers row sr = lane>>1, 64B half (lane&1) of each
    // 128B k32 row-slice. dst 16B slot c16 is XOR-swizzled with (row&7).
    const int sr = lane >> 1;
    const int sc = (lane & 1) * 4;                 // first 16B slot of this half
    const char* gsrc = reinterpret_cast<const char*>(
        W + ((size_t)(b * NN + m0 + sr)) * NN + kq) + sc * 16;
    const uint32_t ringb = smem_u32(&sring[w][0][0]) + sr * 128;
    uint32_t dsts[4];
#pragma unroll
    for (int q = 0; q < 4; ++q)
        dsts[q] = ringb + (((sc + q) ^ (sr & 7)) << 4);

    const float* Ab = g_Afrag + ((size_t)(b * 128 + (kq >> 5)) * 4) * 128 + lane * 4;

    // ---- fill ring stages 0..PFD-1 (one commit group per stage) ----
#pragma unroll
    for (int s = 0; s < PFD; ++s) {
        const char* src = gsrc + (size_t)s * 128;
#pragma unroll
        for (int q = 0; q < 4; ++q)
            cp16(dsts[q] + s * 2048, src + q * 16);
        cp_commit();
    }

    float4 rA[2][4];
#pragma unroll
    for (int q = 0; q < 4; ++q)
        rA[0][q] = __ldg(reinterpret_cast<const float4*>(Ab + q * 128));

    float acc[2][4] = {{0.f,0.f,0.f,0.f},{0.f,0.f,0.f,0.f}};
    float rs0 = 0.f, rs1 = 0.f;

    int cur = 0, pre = PFD;                        // ring slots (mod NST)
    const float4* ring4 = reinterpret_cast<const float4*>(&sring[w][0][0]);
    const int slotA = (2 * tg) ^ gr;               // swizzled 16B slots for this lane
    const int slotB = (2 * tg + 1) ^ gr;

#pragma unroll 1
    for (int i = 0; i < HS; ++i) {
        // ---- issue stage i+PFD (empty group near the tail keeps counts exact) ----
        if (i + PFD < HS) {
            const char* src = gsrc + (size_t)(i + PFD) * 128;
#pragma unroll
            for (int q = 0; q < 4; ++q)
                cp16(dsts[q] + pre * 2048, src + q * 16);
        }
        cp_commit();
        cp_wait4();                                // stage i complete
        __syncwarp();
        // ---- prefetch A for step i+1 ----
        const int hn = (i + 1 < HS) ? i + 1 : 0;
        const float* ap = Ab + (size_t)hn * 512;
#pragma unroll
        for (int q = 0; q < 4; ++q)
            rA[(i & 1) ^ 1][q] = __ldg(reinterpret_cast<const float4*>(ap + q * 128));
        // ---- consume stage i from ring slot cur ----
        const float4 A0 = rA[i & 1][0], A1 = rA[i & 1][1];
        const float4 A2 = rA[i & 1][2], A3 = rA[i & 1][3];
        const float4* sb = ring4 + cur * 128;      // 128 float4 per stage
        {
            const float4 f0 = sb[gr * 8 + slotA];
            const float4 f1 = sb[gr * 8 + slotB];
            uint32_t t0 = thr(f0.x), t1 = thr(f0.y), t2 = thr(f0.z), t3 = thr(f0.w);
            uint32_t t4 = thr(f1.x), t5 = thr(f1.y), t6 = thr(f1.z), t7 = thr(f1.w);
            rs0 += ((uf(t0) + uf(t1)) + (uf(t2) + uf(t3))) +
                   ((uf(t4) + uf(t5)) + (uf(t6) + uf(t7)));
            mma_tf32(acc[0], fu(A0.x), fu(A0.y), fu(A0.z), fu(A0.w), t0, t1);
            mma_tf32(acc[0], fu(A1.x), fu(A1.y), fu(A1.z), fu(A1.w), t2, t3);
            mma_tf32(acc[0], fu(A2.x), fu(A2.y), fu(A2.z), fu(A2.w), t4, t5);
            mma_tf32(acc[0], fu(A3.x), fu(A3.y), fu(A3.z), fu(A3.w), t6, t7);
        }
        {
            const float4 f0 = sb[(8 + gr) * 8 + slotA];
            const float4 f1 = sb[(8 + gr) * 8 + slotB];
            uint32_t t0 = thr(f0.x), t1 = thr(f0.y), t2 = thr(f0.z), t3 = thr(f0.w);
            uint32_t t4 = thr(f1.x), t5 = thr(f1.y), t6 = thr(f1.z), t7 = thr(f1.w);
            rs1 += ((uf(t0) + uf(t1)) + (uf(t2) + uf(t3))) +
                   ((uf(t4) + uf(t5)) + (uf(t6) + uf(t7)));
            mma_tf32(acc[1], fu(A0.x), fu(A0.y), fu(A0.z), fu(A0.w), t0, t1);
            mma_tf32(acc[1], fu(A1.x), fu(A1.y), fu(A1.z), fu(A1.w), t2, t3);
            mma_tf32(acc[1], fu(A2.x), fu(A2.y), fu(A2.z), fu(A2.w), t4, t5);
            mma_tf32(acc[1], fu(A3.x), fu(A3.y), fu(A3.z), fu(A3.w), t6, t7);
        }
        cur = (cur + 1 == NST) ? 0 : cur + 1;
        pre = (pre + 1 == NST) ? 0 : pre + 1;
    }

    // rowsum quad-reduce: all lanes of quad gr end with rs(m = nt*8 + gr)
    rs0 += __shfl_xor_sync(0xffffffffu, rs0, 1);
    rs0 += __shfl_xor_sync(0xffffffffu, rs0, 2);
    rs1 += __shfl_xor_sync(0xffffffffu, rs1, 1);
    rs1 += __shfl_xor_sync(0xffffffffu, rs1, 2);

    // combine K-quarter partials across the 4 warps
    if (w > 0) {
        float* d = sred[w - 1][lane];
#pragma unroll
        for (int nt = 0; nt < 2; ++nt)
#pragma unroll
            for (int c = 0; c < 4; ++c) d[nt * 4 + c] = acc[nt][c];
        d[8] = rs0; d[9] = rs1;
    }
    __syncthreads();
    if (w == 0) {
#pragma unroll
        for (int s = 0; s < 3; ++s) {
            const float* sp = sred[s][lane];
#pragma unroll
            for (int nt = 0; nt < 2; ++nt)
#pragma unroll
                for (int c = 0; c < 4; ++c) acc[nt][c] += sp[nt * 4 + c];
            rs0 += sp[8]; rs1 += sp[9];
        }
        const float i00 = 1.0f / __shfl_sync(0xffffffffu, rs0, 8 * tg);
        const float i01 = 1.0f / __shfl_sync(0xffffffffu, rs0, 8 * tg + 4);
        const float i10 = 1.0f / __shfl_sync(0xffffffffu, rs1, 8 * tg);
        const float i11 = 1.0f / __shfl_sync(0xffffffffu, rs1, 8 * tg + 4);
        // acc[nt][c]: d = gr + 8*(c>=2), m = m0 + nt*8 + 2tg + (c&1)
        float* ob = out + (size_t)b * ND * NN;
#pragma unroll
        for (int nt = 0; nt < 2; ++nt) {
#pragma unroll
            for (int c = 0; c < 4; ++c) {
                const int dd = gr + ((c >= 2) ? 8 : 0);
                const int m  = m0 + nt * 8 + 2 * tg + (c & 1);
                const float inv = nt ? ((c & 1) ? i11 : i10)
                                     : ((c & 1) ? i01 : i00);
                ob[(size_t)dd * NN + m] = acc[nt][c] * inv;
            }
        }
    }
}

extern "C" void kernel_launch(void* const* d_in, const int* in_sizes, int n_in,
                              void* d_out, int out_size) {
    const float* seg = (const float*)d_in[0];   // [4,16,64,64] fp32
    const float* W   = (const float*)d_in[1];   // [4,4096,4096] fp32
    float* out = (float*)d_out;                 // [4,16,64,64] fp32
    (void)in_sizes; (void)n_in; (void)out_size;

    build_afrag_kernel<<<256, 256>>>(seg);
    regu_mma_kernel<<<NB * (NN / 16), 128>>>(W, out);
}

// round 15
// speedup vs baseline: 1.8334x; 1.8334x over previous
#include <cuda_runtime.h>
#include <cstdint>

#define THRESH 0.85f
#define NB 4
#define ND 16
#define NN 4096
#define HS 32           // k32 steps per warp (K quarter = 1024)

// A-fragment table (S = tf32(seg), permuted k): [b][c32 0..127][ks 0..3][lane][4]
// physical k = c32*32 + 8*tg + 2*ks + (j>>1); row = gr + 8*(j&1). 1 MB, L2-resident.
__device__ float g_Afrag[NB * 128 * 4 * 32 * 4];

__device__ __forceinline__ uint32_t cvt_tf32(float x) {
    uint32_t u; asm("cvt.rna.tf32.f32 %0, %1;" : "=r"(u) : "f"(x));
    return u;
}
// threshold only; HMMA's tf32 datapath truncates low mantissa bits in HW
__device__ __forceinline__ uint32_t thr(float w) {
    float wt = (w > THRESH) ? w : 0.0f;
    return __float_as_uint(wt);
}
__device__ __forceinline__ void mma_tf32(float (&c)[4], uint32_t a0, uint32_t a1,
                                         uint32_t a2, uint32_t a3,
                                         uint32_t b0, uint32_t b1) {
    asm volatile(
        "mma.sync.aligned.m16n8k8.row.col.f32.tf32.tf32.f32 "
        "{%0,%1,%2,%3}, {%4,%5,%6,%7}, {%8,%9}, {%0,%1,%2,%3};"
        : "+f"(c[0]), "+f"(c[1]), "+f"(c[2]), "+f"(c[3])
        : "r"(a0), "r"(a1), "r"(a2), "r"(a3), "r"(b0), "r"(b1));
}
__device__ __forceinline__ uint32_t fu(float x) { return __float_as_uint(x); }
__device__ __forceinline__ float uf(uint32_t x) { return __uint_as_float(x); }

// ---------------- prologue: build permuted A-fragment table ----------------
__global__ void __launch_bounds__(256) build_afrag_kernel(const float* __restrict__ seg) {
    int idx  = blockIdx.x * 256 + threadIdx.x;    // [b][c][ks][lane], 65536 total
    int lane = idx & 31;
    int ks   = (idx >> 5) & 3;
    int c    = (idx >> 7) & 127;
    int b    = idx >> 14;
    int gr = lane >> 2, tg = lane & 3;
    int k  = c * 32 + 8 * tg + 2 * ks;
    const float* sp = seg + ((size_t)b * ND << 12);
    float4 v;
    v.x = uf(cvt_tf32(sp[((size_t)gr       << 12) + k]));
    v.y = uf(cvt_tf32(sp[((size_t)(gr + 8) << 12) + k]));
    v.z = uf(cvt_tf32(sp[((size_t)gr       << 12) + k + 1]));
    v.w = uf(cvt_tf32(sp[((size_t)(gr + 8) << 12) + k + 1]));
    reinterpret_cast<float4*>(g_Afrag)[idx] = v;
}

// ---------------- main kernel ----------------
// grid = 512 CTAs (4 b x 128 tiles of 32 m-rows), block = 256 thr = 8 warps.
// Warp w = (quarter q = w>>1, m-half h = w&1): rows m0+h*16..+15, K quarter
// [q*1024,(q+1)*1024) as 32 k32-steps. The two warps of a quarter-pair read
// IDENTICAL A fragments -> L1/MSHR dedup halves A-side L2 traffic. Per-warp
// dataflow identical to the verified R12 kernel (W thresholded in registers
// as the B operand of m16n8k8 tf32 MMA; W and A double-buffered).
__global__ void __launch_bounds__(256, 2) regu_mma_kernel(const float* __restrict__ W,
                                                          float* __restrict__ out) {
    __shared__ float sred[6][32][10];
    const int tid  = threadIdx.x;
    const int w    = tid >> 5;
    const int lane = tid & 31;
    const int gr   = lane >> 2;
    const int tg   = lane & 3;
    const int q    = w >> 1;             // K quarter
    const int h    = w & 1;              // m-half
    const int b    = blockIdx.x >> 7;
    const int m0   = ((blockIdx.x & 127) << 5) + h * 16;
    const int kq   = q << 10;

    // B-operand row pointers: lane (gr,tg) reads W rows m0+gr / m0+8+gr, slice 8*tg
    const float* Wb0 = W + ((size_t)(b * NN + m0 + gr)) * NN + kq + 8 * tg;
    const float* Wb1 = Wb0 + (size_t)8 * NN;
    const float* Ab  = g_Afrag + ((size_t)(b * 128 + (kq >> 5)) * 4) * 128 + lane * 4;

    float4 rW[2][4];   // [buf][nt*2+j]
    float4 rA[2][4];   // [buf][ks]
#pragma unroll
    for (int j = 0; j < 2; ++j) {
        rW[0][j]     = __ldg(reinterpret_cast<const float4*>(Wb0 + j * 4));
        rW[0][2 + j] = __ldg(reinterpret_cast<const float4*>(Wb1 + j * 4));
    }
#pragma unroll
    for (int p = 0; p < 4; ++p)
        rA[0][p] = __ldg(reinterpret_cast<const float4*>(Ab + p * 128));

    float acc[2][4] = {{0.f,0.f,0.f,0.f},{0.f,0.f,0.f,0.f}};
    float rs0 = 0.f, rs1 = 0.f;

#pragma unroll 2
    for (int hs = 0; hs < HS; ++hs) {
        const int p  = hs & 1;
        const int hn = (hs + 1 < HS) ? hs + 1 : 0;   // harmless wrap on last iter
        // ---- prefetch h-step hn into the other buffer ----
        const float* wp0 = Wb0 + hn * 32;
        const float* wp1 = Wb1 + hn * 32;
#pragma unroll
        for (int j = 0; j < 2; ++j) {
            rW[p ^ 1][j]     = __ldg(reinterpret_cast<const float4*>(wp0 + j * 4));
            rW[p ^ 1][2 + j] = __ldg(reinterpret_cast<const float4*>(wp1 + j * 4));
        }
        const float* ap = Ab + (size_t)hn * 512;
#pragma unroll
        for (int z = 0; z < 4; ++z)
            rA[p ^ 1][z] = __ldg(reinterpret_cast<const float4*>(ap + z * 128));
        // ---- compute on buffer p ----
        const float4 A0 = rA[p][0], A1 = rA[p][1], A2 = rA[p][2], A3 = rA[p][3];
#pragma unroll
        for (int nt = 0; nt < 2; ++nt) {
            const float4 f0 = rW[p][2 * nt], f1 = rW[p][2 * nt + 1];
            uint32_t t0 = thr(f0.x), t1 = thr(f0.y);
            uint32_t t2 = thr(f0.z), t3 = thr(f0.w);
            uint32_t t4 = thr(f1.x), t5 = thr(f1.y);
            uint32_t t6 = thr(f1.z), t7 = thr(f1.w);
            float s = ((uf(t0) + uf(t1)) + (uf(t2) + uf(t3))) +
                      ((uf(t4) + uf(t5)) + (uf(t6) + uf(t7)));
            if (nt == 0) rs0 += s; else rs1 += s;
            mma_tf32(acc[nt], fu(A0.x), fu(A0.y), fu(A0.z), fu(A0.w), t0, t1);
            mma_tf32(acc[nt], fu(A1.x), fu(A1.y), fu(A1.z), fu(A1.w), t2, t3);
            mma_tf32(acc[nt], fu(A2.x), fu(A2.y), fu(A2.z), fu(A2.w), t4, t5);
            mma_tf32(acc[nt], fu(A3.x), fu(A3.y), fu(A3.z), fu(A3.w), t6, t7);
        }
    }

    // rowsum quad-reduce: all lanes of quad gr end with rs(m = nt*8 + gr)
    rs0 += __shfl_xor_sync(0xffffffffu, rs0, 1);
    rs0 += __shfl_xor_sync(0xffffffffu, rs0, 2);
    rs1 += __shfl_xor_sync(0xffffffffu, rs1, 1);
    rs1 += __shfl_xor_sync(0xffffffffu, rs1, 2);

    // combine K-quarter partials: warps with q>0 publish; q==0 warps finalize.
    if (q > 0) {
        float* d = sred[(q - 1) * 2 + h][lane];
#pragma unroll
        for (int nt = 0; nt < 2; ++nt)
#pragma unroll
            for (int c = 0; c < 4; ++c) d[nt * 4 + c] = acc[nt][c];
        d[8] = rs0; d[9] = rs1;
    }
    __syncthreads();
    if (q == 0) {
#pragma unroll
        for (int s = 0; s < 3; ++s) {
            const float* sp = sred[s * 2 + h][lane];
#pragma unroll
            for (int nt = 0; nt < 2; ++nt)
#pragma unroll
                for (int c = 0; c < 4; ++c) acc[nt][c] += sp[nt * 4 + c];
            rs0 += sp[8]; rs1 += sp[9];
        }
        const float i00 = 1.0f / __shfl_sync(0xffffffffu, rs0, 8 * tg);
        const float i01 = 1.0f / __shfl_sync(0xffffffffu, rs0, 8 * tg + 4);
        const float i10 = 1.0f / __shfl_sync(0xffffffffu, rs1, 8 * tg);
        const float i11 = 1.0f / __shfl_sync(0xffffffffu, rs1, 8 * tg + 4);
        // acc[nt][c]: d = gr + 8*(c>=2), m = m0 + nt*8 + 2tg + (c&1)
        float* ob = out + (size_t)b * ND * NN;
#pragma unroll
        for (int nt = 0; nt < 2; ++nt) {
#pragma unroll
            for (int c = 0; c < 4; ++c) {
                const int dd = gr + ((c >= 2) ? 8 : 0);
                const int m  = m0 + nt * 8 + 2 * tg + (c & 1);
                const float inv = nt ? ((c & 1) ? i11 : i10)
                                     : ((c & 1) ? i01 : i00);
                ob[(size_t)dd * NN + m] = acc[nt][c] * inv;
            }
        }
    }
}

extern "C" void kernel_launch(void* const* d_in, const int* in_sizes, int n_in,
                              void* d_out, int out_size) {
    const float* seg = (const float*)d_in[0];   // [4,16,64,64] fp32
    const float* W   = (const float*)d_in[1];   // [4,4096,4096] fp32
    float* out = (float*)d_out;                 // [4,16,64,64] fp32
    (void)in_sizes; (void)n_in; (void)out_size;

    build_afrag_kernel<<<256, 256>>>(seg);
    regu_mma_kernel<<<NB * (NN / 32), 256>>>(W, out);
}